// round 1
// baseline (speedup 1.0000x reference)
#include <cuda_runtime.h>
#include <cuda_bf16.h>

// Problem constants (B=4, N=4096, D=256)
#define Bz 4
#define Nn 4096
#define Dd 256
#define ROWS (Bz * Nn)          // 16384
#define NEG_INF_F (-9e15f)
#define ALPHA_F 0.2f

// ---------------- device scratch (static, allocation-free) ----------------
__device__ float g_u1[Dd];
__device__ float g_u2[Dd];
__device__ float g_Ax[ROWS];
__device__ float g_Ay[ROWS];
__device__ float g_m[ROWS];
__device__ float g_invs[ROWS];
__device__ unsigned g_bits[(size_t)ROWS * (Nn / 32)];   // 8 MB bitmask
__device__ float g_hp[(size_t)ROWS * Dd];               // 16 MB h_prime

// ---------------- K0: u1 = W @ a1, u2 = W @ a2 ----------------
__global__ void k_u(const float* __restrict__ W,
                    const float* __restrict__ a1,
                    const float* __restrict__ a2) {
    __shared__ float s1[Dd], s2[Dd];
    int t = threadIdx.x;
    s1[t] = a1[t];
    s2[t] = a2[t];
    __syncthreads();
    const float* row = W + (size_t)t * Dd;
    float acc1 = 0.f, acc2 = 0.f;
    #pragma unroll 8
    for (int d = 0; d < Dd; d++) {
        float w = row[d];
        acc1 += w * s1[d];
        acc2 += w * s2[d];
    }
    g_u1[t] = acc1;
    g_u2[t] = acc2;
}

// ---------------- K1: Ax[r] = feat[r]·u1, Ay[r] = feat[r]·u2 ----------------
// one warp per row
__global__ void __launch_bounds__(256) k_axay(const float* __restrict__ feat) {
    int row  = blockIdx.x * 8 + (threadIdx.x >> 5);
    int lane = threadIdx.x & 31;
    const float* f = feat + (size_t)row * Dd;
    float a = 0.f, b = 0.f;
    #pragma unroll
    for (int k = lane; k < Dd; k += 32) {
        float v = f[k];
        a += v * g_u1[k];
        b += v * g_u2[k];
    }
    #pragma unroll
    for (int o = 16; o; o >>= 1) {
        a += __shfl_xor_sync(0xffffffffu, a, o);
        b += __shfl_xor_sync(0xffffffffu, b, o);
    }
    if (lane == 0) { g_Ax[row] = a; g_Ay[row] = b; }
}

// ---------------- K2: per-row softmax stats + adj bit-pack ----------------
// one block (256 threads) per row; each thread owns 16 consecutive j.
// Single 268 MB streaming read of adj. Masked entries use value NEG_INF,
// exactly matching jnp.where + softmax semantics (including the degenerate
// all-masked row's m = NEG_INF, s = N behavior in the stats).
__global__ void __launch_bounds__(256) k_rowstats(const int* __restrict__ adj) {
    int row = blockIdx.x;
    int b   = row >> 12;
    int t   = threadIdx.x;

    __shared__ float sAx[Nn];
    __shared__ float sred[16];

    // stage Ax for this batch (reused by all 256 threads)
    const float4* Axb4 = (const float4*)(g_Ax + (size_t)b * Nn);
    float4* sAx4 = (float4*)sAx;
    for (int j = t; j < Nn / 4; j += 256) sAx4[j] = Axb4[j];
    __syncthreads();

    float Ay = g_Ay[row];
    const int4* arow = (const int4*)(adj + (size_t)row * Nn);

    float e[16];
    unsigned msk = 0u;
    float mx = -3.4e38f;
    #pragma unroll
    for (int q = 0; q < 4; q++) {
        int4 a4 = arow[t * 4 + q];
        int jb = t * 16 + q * 4;
        int av[4] = { a4.x, a4.y, a4.z, a4.w };
        #pragma unroll
        for (int r = 0; r < 4; r++) {
            float v  = sAx[jb + r] + Ay;
            float ee = v > 0.f ? v : ALPHA_F * v;
            bool on  = av[r] > 0;
            if (on) msk |= (1u << (q * 4 + r));
            float val = on ? ee : NEG_INF_F;
            e[q * 4 + r] = val;
            mx = fmaxf(mx, val);
        }
    }

    // pack 32 j-bits per word: even thread = low 16, odd thread = high 16
    unsigned other = __shfl_xor_sync(0xffffffffu, msk, 1);
    if ((t & 1) == 0)
        g_bits[(size_t)row * (Nn / 32) + (t >> 1)] = msk | (other << 16);

    // block max
    #pragma unroll
    for (int o = 16; o; o >>= 1) mx = fmaxf(mx, __shfl_xor_sync(0xffffffffu, mx, o));
    if ((t & 31) == 0) sred[t >> 5] = mx;
    __syncthreads();
    if (t == 0) {
        float v = sred[0];
        #pragma unroll
        for (int w = 1; w < 8; w++) v = fmaxf(v, sred[w]);
        sred[8] = v;
    }
    __syncthreads();
    float m = sred[8];

    // block sum of exp(e - m)   (masked: exp(NEG_INF - m) -> 0; degenerate: 1)
    float s = 0.f;
    #pragma unroll
    for (int q = 0; q < 16; q++) s += __expf(e[q] - m);
    #pragma unroll
    for (int o = 16; o; o >>= 1) s += __shfl_xor_sync(0xffffffffu, s, o);
    __syncthreads();
    if ((t & 31) == 0) sred[t >> 5] = s;
    __syncthreads();
    if (t == 0) {
        float v = 0.f;
        #pragma unroll
        for (int w = 0; w < 8; w++) v += sred[w];
        g_m[row]    = m;
        g_invs[row] = 1.f / v;
    }
}

// ---------------- K3: h_prime = attention @ feat ----------------
// CTA tile 128 rows x 128 d-cols, K-chunks of 32. Attention probabilities are
// reconstructed on the fly from {bits, Ax, Ay, m, 1/s} into SMEM, then a
// classic 8x8 register-blocked fp32 GEMM consumes them against a feat tile.
__global__ void __launch_bounds__(256) k_attn_feat(const float* __restrict__ feat) {
    const int dtile   = blockIdx.x;        // 0..1
    const int rowtile = blockIdx.y;        // 0..127
    const int rowbase = rowtile * 128;
    const int b       = rowbase >> 12;     // 4096 % 128 == 0: tiles never straddle batches
    const float* featb = feat + (size_t)b * Nn * Dd;
    const float* Axb   = g_Ax + (size_t)b * Nn;

    const int t  = threadIdx.x;
    const int ip = t >> 1;                 // row (0..127) this thread builds P for
    const int jh = t & 1;                  // which 16-j half of the 32-chunk
    const int grow = rowbase + ip;
    const float Ay   = g_Ay[grow];
    const float m    = g_m[grow];
    const float invs = g_invs[grow];
    const unsigned* bitsrow = g_bits + (size_t)grow * (Nn / 32);

    __shared__ float sP[128][33];          // padded: conflict-free column reads
    __shared__ float sF[32][128];

    float acc[8][8];
    #pragma unroll
    for (int r = 0; r < 8; r++)
        #pragma unroll
        for (int c = 0; c < 8; c++) acc[r][c] = 0.f;

    const int ty = t >> 4, tx = t & 15;    // 16x16 thread grid, 8x8 micro-tile
    const int d0 = dtile * 128;

    for (int j0 = 0; j0 < Nn; j0 += 32) {
        // --- build P[128][32] for this chunk ---
        unsigned w    = bitsrow[j0 >> 5];
        unsigned half = jh ? (w >> 16) : (w & 0xffffu);
        int jb = j0 + jh * 16;
        #pragma unroll
        for (int q = 0; q < 16; q++) {
            float v  = Axb[jb + q] + Ay;
            float ee = v > 0.f ? v : ALPHA_F * v;
            float p  = ((half >> q) & 1u) ? __expf(ee - m) * invs : 0.f;
            sP[ip][jh * 16 + q] = p;
        }
        // --- stage feat[j0..j0+31, d0..d0+127] ---
        #pragma unroll
        for (int q = 0; q < 4; q++) {
            int f4 = t + q * 256;          // 1024 float4s
            int jr = f4 >> 5;              // 32 float4 per row
            int dc = (f4 & 31) << 2;
            *(float4*)&sF[jr][dc] =
                *(const float4*)(featb + (size_t)(j0 + jr) * Dd + d0 + dc);
        }
        __syncthreads();

        #pragma unroll
        for (int kk = 0; kk < 32; kk++) {
            float pr[8];
            #pragma unroll
            for (int r = 0; r < 8; r++) pr[r] = sP[ty * 8 + r][kk];
            float4 f0 = *(float4*)&sF[kk][tx * 8];
            float4 f1 = *(float4*)&sF[kk][tx * 8 + 4];
            float fr[8] = { f0.x, f0.y, f0.z, f0.w, f1.x, f1.y, f1.z, f1.w };
            #pragma unroll
            for (int r = 0; r < 8; r++)
                #pragma unroll
                for (int c = 0; c < 8; c++) acc[r][c] += pr[r] * fr[c];
        }
        __syncthreads();
    }

    #pragma unroll
    for (int r = 0; r < 8; r++) {
        float* dst = g_hp + (size_t)(rowbase + ty * 8 + r) * Dd + d0 + tx * 8;
        *(float4*)dst       = make_float4(acc[r][0], acc[r][1], acc[r][2], acc[r][3]);
        *(float4*)(dst + 4) = make_float4(acc[r][4], acc[r][5], acc[r][6], acc[r][7]);
    }
}

// ---------------- K4: out = elu(h_prime @ W) ----------------
__global__ void __launch_bounds__(256) k_out(const float* __restrict__ W,
                                             float* __restrict__ out) {
    const int dtile   = blockIdx.x;
    const int rowtile = blockIdx.y;
    const int rowbase = rowtile * 128;
    const int t = threadIdx.x;
    const int ty = t >> 4, tx = t & 15;
    const int d0 = dtile * 128;

    __shared__ float sA[128][33];
    __shared__ float sW[32][128];

    float acc[8][8];
    #pragma unroll
    for (int r = 0; r < 8; r++)
        #pragma unroll
        for (int c = 0; c < 8; c++) acc[r][c] = 0.f;

    for (int k0 = 0; k0 < Dd; k0 += 32) {
        // stage A = h_prime[rowbase..+127, k0..k0+31]
        #pragma unroll
        for (int q = 0; q < 4; q++) {
            int f4 = t + q * 256;          // 1024 float4s
            int jr = f4 >> 3;              // 8 float4 per row
            int kc = (f4 & 7) << 2;
            float4 v = *(const float4*)(g_hp + (size_t)(rowbase + jr) * Dd + k0 + kc);
            sA[jr][kc] = v.x; sA[jr][kc + 1] = v.y;
            sA[jr][kc + 2] = v.z; sA[jr][kc + 3] = v.w;
        }
        // stage W[k0..k0+31, d0..d0+127]
        #pragma unroll
        for (int q = 0; q < 4; q++) {
            int f4 = t + q * 256;
            int kr = f4 >> 5;
            int dc = (f4 & 31) << 2;
            *(float4*)&sW[kr][dc] =
                *(const float4*)(W + (size_t)(k0 + kr) * Dd + d0 + dc);
        }
        __syncthreads();

        #pragma unroll
        for (int kk = 0; kk < 32; kk++) {
            float pr[8];
            #pragma unroll
            for (int r = 0; r < 8; r++) pr[r] = sA[ty * 8 + r][kk];
            float4 f0 = *(float4*)&sW[kk][tx * 8];
            float4 f1 = *(float4*)&sW[kk][tx * 8 + 4];
            float fr[8] = { f0.x, f0.y, f0.z, f0.w, f1.x, f1.y, f1.z, f1.w };
            #pragma unroll
            for (int r = 0; r < 8; r++)
                #pragma unroll
                for (int c = 0; c < 8; c++) acc[r][c] += pr[r] * fr[c];
        }
        __syncthreads();
    }

    #pragma unroll
    for (int r = 0; r < 8; r++) {
        #pragma unroll
        for (int c = 0; c < 8; c++) {
            float x = acc[r][c];
            acc[r][c] = x > 0.f ? x : expm1f(x);   // ELU (alpha = 1)
        }
        float* dst = out + (size_t)(rowbase + ty * 8 + r) * Dd + d0 + tx * 8;
        *(float4*)dst       = make_float4(acc[r][0], acc[r][1], acc[r][2], acc[r][3]);
        *(float4*)(dst + 4) = make_float4(acc[r][4], acc[r][5], acc[r][6], acc[r][7]);
    }
}

// ---------------- launch ----------------
extern "C" void kernel_launch(void* const* d_in, const int* in_sizes, int n_in,
                              void* d_out, int out_size) {
    const float* feat = (const float*)d_in[0];
    const int*   adj  = (const int*)d_in[1];
    const float* W    = (const float*)d_in[2];
    const float* a1   = (const float*)d_in[3];
    const float* a2   = (const float*)d_in[4];
    float* out = (float*)d_out;

    k_u<<<1, 256>>>(W, a1, a2);
    k_axay<<<ROWS / 8, 256>>>(feat);
    k_rowstats<<<ROWS, 256>>>(adj);
    dim3 g(2, ROWS / 128);
    k_attn_feat<<<g, 256>>>(feat);
    k_out<<<g, 256>>>(W, out);
}

// round 3
// speedup vs baseline: 2.1336x; 2.1336x over previous
#include <cuda_runtime.h>
#include <cuda_bf16.h>
#include <cstdint>

// Problem constants (B=4, N=4096, D=256)
#define Bz 4
#define Nn 4096
#define Dd 256
#define ROWS (Bz * Nn)          // 16384
#define ALPHA_F 0.2f

// ---------------- device scratch (static, allocation-free) ----------------
__device__ float g_u1[Dd], g_u2[Dd];
__device__ float g_Ax[ROWS], g_Ay[ROWS];
__device__ float g_E1[ROWS], g_E2[ROWS];                // exp(Ax), exp(0.2 Ax)
__device__ float g_F1[ROWS], g_F2[ROWS], g_T[ROWS];     // per-row softmax factors
__device__ unsigned g_bits[(size_t)ROWS * (Nn / 32)];   // 8 MB adjacency bitmask
__device__ float g_hp[(size_t)ROWS * Dd];               // 16 MB h_prime
__device__ float g_FT[(size_t)Bz * Dd * Nn];            // 16 MB feat^T (tf32-rounded)

// ---------------- helpers ----------------
__device__ __forceinline__ uint32_t smem_u32(const void* p) {
    uint32_t a;
    asm("{ .reg .u64 t; cvta.to.shared.u64 t, %1; cvt.u32.u64 %0, t; }" : "=r"(a) : "l"(p));
    return a;
}
__device__ __forceinline__ float to_tf32(float x) {
    uint32_t u;
    asm("cvt.rna.tf32.f32 %0, %1;" : "=r"(u) : "f"(x));
    return __uint_as_float(u);
}
__device__ __forceinline__ void cp_async16(uint32_t dst, const void* src) {
    asm volatile("cp.async.cg.shared.global [%0], [%1], 16;" :: "r"(dst), "l"(src));
}
#define CP_COMMIT()  asm volatile("cp.async.commit_group;" ::: "memory")
#define CP_WAIT(n)   asm volatile("cp.async.wait_group %0;" :: "n"(n) : "memory")

// m16n8k8 tf32 warp MMA: D(16x8,f32) += A(16x8,tf32 row) * B(8x8,tf32 col)
__device__ __forceinline__ void mma_tf32(float* c, uint32_t a0, uint32_t a1,
                                         uint32_t a2, uint32_t a3,
                                         uint32_t b0, uint32_t b1) {
    asm volatile(
        "mma.sync.aligned.m16n8k8.row.col.f32.tf32.tf32.f32 "
        "{%0,%1,%2,%3}, {%4,%5,%6,%7}, {%8,%9}, {%0,%1,%2,%3};"
        : "+f"(c[0]), "+f"(c[1]), "+f"(c[2]), "+f"(c[3])
        : "r"(a0), "r"(a1), "r"(a2), "r"(a3), "r"(b0), "r"(b1));
}

// ---------------- K0: u1 = W @ a1, u2 = W @ a2 ----------------
__global__ void k_u(const float* __restrict__ W, const float* __restrict__ a1,
                    const float* __restrict__ a2) {
    __shared__ float s1[Dd], s2[Dd];
    int t = threadIdx.x;
    s1[t] = a1[t]; s2[t] = a2[t];
    __syncthreads();
    const float* row = W + (size_t)t * Dd;
    float acc1 = 0.f, acc2 = 0.f;
    #pragma unroll 8
    for (int d = 0; d < Dd; d++) { float w = row[d]; acc1 += w * s1[d]; acc2 += w * s2[d]; }
    g_u1[t] = acc1; g_u2[t] = acc2;
}

// ---------------- K1: Ax, Ay ----------------
__global__ void __launch_bounds__(256) k_axay(const float* __restrict__ feat) {
    int row = blockIdx.x * 8 + (threadIdx.x >> 5);
    int lane = threadIdx.x & 31;
    const float* f = feat + (size_t)row * Dd;
    float a = 0.f, b = 0.f;
    #pragma unroll
    for (int k = lane; k < Dd; k += 32) { float v = f[k]; a += v * g_u1[k]; b += v * g_u2[k]; }
    #pragma unroll
    for (int o = 16; o; o >>= 1) {
        a += __shfl_xor_sync(0xffffffffu, a, o);
        b += __shfl_xor_sync(0xffffffffu, b, o);
    }
    if (lane == 0) { g_Ax[row] = a; g_Ay[row] = b; }
}

// ---------------- K1b: E1/E2 ----------------
__global__ void k_exp() {
    int i = blockIdx.x * 256 + threadIdx.x;
    float a = g_Ax[i];
    g_E1[i] = expf(a);
    g_E2[i] = expf(ALPHA_F * a);
}

// ---------------- K1c: feat^T (tf32-rounded, j-major rows of d) ----------------
__global__ void k_transpose(const float* __restrict__ feat) {
    __shared__ float tile[32][33];
    int j0 = blockIdx.x * 32, d0 = blockIdx.y * 32, b = blockIdx.z;
    int tx = threadIdx.x, ty = threadIdx.y;
    const float* fb = feat + (size_t)b * Nn * Dd;
    #pragma unroll
    for (int r = 0; r < 4; r++)
        tile[ty + r * 8][tx] = fb[(size_t)(j0 + ty + r * 8) * Dd + d0 + tx];
    __syncthreads();
    float* ob = g_FT + (size_t)b * Dd * Nn;
    #pragma unroll
    for (int r = 0; r < 4; r++)
        ob[(size_t)(d0 + ty + r * 8) * Nn + j0 + tx] = to_tf32(tile[tx][ty + r * 8]);
}

// ---------------- K2: row stats + bitmask (exp-free streaming pass) ----------------
__global__ void __launch_bounds__(256) k_rowstats(const int* __restrict__ adj) {
    extern __shared__ float dynrs[];     // sAx | sE1 | sE2 (3 * 4096 floats)
    float* sAx = dynrs;
    float* sE1 = dynrs + Nn;
    float* sE2 = dynrs + 2 * Nn;
    __shared__ float srM[8], srS1[8], srS2[8];

    int rb = blockIdx.x * 8;
    int b  = rb >> 12;
    int t  = threadIdx.x;

    const float4* gA = (const float4*)(g_Ax + (size_t)b * Nn);
    const float4* g1 = (const float4*)(g_E1 + (size_t)b * Nn);
    const float4* g2 = (const float4*)(g_E2 + (size_t)b * Nn);
    for (int i = t; i < Nn / 4; i += 256) {
        ((float4*)sAx)[i] = gA[i];
        ((float4*)sE1)[i] = g1[i];
        ((float4*)sE2)[i] = g2[i];
    }
    __syncthreads();

    for (int rr = 0; rr < 8; rr++) {
        int row = rb + rr;
        float Ay = g_Ay[row];
        float T  = __expf(-Ay);
        const int4* arow = (const int4*)(adj + (size_t)row * Nn);

        unsigned msk = 0u;
        float mxAx = -3.4e38f, S1 = 0.f, S2 = 0.f;
        #pragma unroll
        for (int q = 0; q < 4; q++) {
            int4 a4 = arow[t * 4 + q];
            int jb = t * 16 + q * 4;
            int av[4] = { a4.x, a4.y, a4.z, a4.w };
            #pragma unroll
            for (int r = 0; r < 4; r++) {
                if (av[r] > 0) {
                    int j = jb + r;
                    msk |= 1u << (q * 4 + r);
                    mxAx = fmaxf(mxAx, sAx[j]);
                    float e1 = sE1[j];
                    if (e1 > T) S1 += e1; else S2 += sE2[j];
                }
            }
        }
        unsigned other = __shfl_xor_sync(0xffffffffu, msk, 1);
        if ((t & 1) == 0)
            g_bits[(size_t)row * (Nn / 32) + (t >> 1)] = msk | (other << 16);

        #pragma unroll
        for (int o = 16; o; o >>= 1) {
            mxAx = fmaxf(mxAx, __shfl_xor_sync(0xffffffffu, mxAx, o));
            S1 += __shfl_xor_sync(0xffffffffu, S1, o);
            S2 += __shfl_xor_sync(0xffffffffu, S2, o);
        }
        if ((t & 31) == 0) { int w = t >> 5; srM[w] = mxAx; srS1[w] = S1; srS2[w] = S2; }
        __syncthreads();
        if (t == 0) {
            float M = srM[0], s1 = srS1[0], s2 = srS2[0];
            #pragma unroll
            for (int w = 1; w < 8; w++) {
                M = fmaxf(M, srM[w]); s1 += srS1[w]; s2 += srS2[w];
            }
            float m0 = Ay + M;
            float m  = m0 > 0.f ? m0 : ALPHA_F * m0;   // leakyrelu(max) = max(leakyrelu)
            float eP = __expf(Ay - m);
            float eN = __expf(ALPHA_F * Ay - m);
            float invs = 1.f / (eP * s1 + eN * s2);
            g_F1[row] = eP * invs;
            g_F2[row] = eN * invs;
            g_T[row]  = T;
        }
        __syncthreads();
    }
}

// ---------------- K3: h_prime = P @ feat via warp-level tf32 MMA ----------------
// CTA: 128 rows x 256 cols, 8 warps (warp tile 64x64), K = 4096 in chunks of 32.
// P reconstructed exp-free in SMEM; feat^T streamed via double-buffered cp.async.
#define PSTR 36
#define OFF_E1 0
#define OFF_E2 4096
#define OFF_P  8192
#define P_SZ   (128 * PSTR)                 // 4608 floats
#define OFF_F  (OFF_P + 2 * P_SZ)           // 17408
#define F_SZ   (256 * PSTR)                 // 9216 floats
#define AT_SMEM_BYTES ((OFF_F + 2 * F_SZ) * 4)   // 143360

__global__ void __launch_bounds__(256, 1) k_attn_mma() {
    extern __shared__ float s[];
    const uint32_t sb = smem_u32(s);
    const int t = threadIdx.x;
    const int wid = t >> 5, lane = t & 31;
    const int g = lane >> 2, tig = lane & 3;
    const int rowbase = blockIdx.x * 128;
    const int b = rowbase >> 12;            // 4096 % 128 == 0
    const float* FTb = g_FT + (size_t)b * Dd * Nn;

    // stage E1/E2 for this batch
    {
        const float4* s1 = (const float4*)(g_E1 + (size_t)b * Nn);
        const float4* s2 = (const float4*)(g_E2 + (size_t)b * Nn);
        #pragma unroll
        for (int i = 0; i < 4; i++) {
            ((float4*)(s + OFF_E1))[t + i * 256] = s1[t + i * 256];
            ((float4*)(s + OFF_E2))[t + i * 256] = s2[t + i * 256];
        }
    }
    const int ip = t >> 1, jh = t & 1;      // P-build role: row ip, 16-j half jh
    const int grow = rowbase + ip;
    const float F1 = g_F1[grow], F2 = g_F2[grow], T = g_T[grow];
    const unsigned* bitsrow = g_bits + (size_t)grow * (Nn / 32);
    const float* sE1 = s + OFF_E1;
    const float* sE2 = s + OFF_E2;
    __syncthreads();

    // prefetch F chunk 0 into buffer 0
    {
        #pragma unroll
        for (int i = 0; i < 8; i++) {
            int f4 = t + i * 256;
            int dr = f4 >> 3, cq = f4 & 7;
            cp_async16(sb + (OFF_F + dr * PSTR + cq * 4) * 4,
                       FTb + (size_t)dr * Nn + cq * 4);
        }
        CP_COMMIT();
    }

    const int mbase = (wid & 1) * 64;
    const int nbase = (wid >> 1) * 64;
    float acc[4][8][4];
    #pragma unroll
    for (int mt = 0; mt < 4; mt++)
        #pragma unroll
        for (int nt = 0; nt < 8; nt++)
            #pragma unroll
            for (int r = 0; r < 4; r++) acc[mt][nt][r] = 0.f;

    for (int c = 0; c < Nn / 32; c++) {
        const int buf = c & 1;
        float* sPb = s + OFF_P + buf * P_SZ;
        float* sFb = s + OFF_F + buf * F_SZ;
        const int j0 = c * 32;

        // build P(c): this thread covers row ip, 16 j-values of half jh
        {
            unsigned wb = bitsrow[c];
            unsigned half = jh ? (wb >> 16) : (wb & 0xffffu);
            const int kb = jh * 16;
            #pragma unroll
            for (int q = 0; q < 4; q++) {
                float v[4];
                #pragma unroll
                for (int r = 0; r < 4; r++) {
                    int jj = q * 4 + r;
                    float e1 = sE1[j0 + kb + jj];
                    float p = (e1 > T) ? e1 * F1 : sE2[j0 + kb + jj] * F2;
                    v[r] = to_tf32(((half >> jj) & 1u) ? p : 0.f);
                }
                *(float4*)&sPb[ip * PSTR + kb + q * 4] =
                    make_float4(v[0], v[1], v[2], v[3]);
            }
        }
        // prefetch F(c+1) into the other buffer
        if (c + 1 < Nn / 32) {
            uint32_t dstb = sb + (OFF_F + (1 - buf) * F_SZ) * 4;
            const float* src = FTb + j0 + 32;
            #pragma unroll
            for (int i = 0; i < 8; i++) {
                int f4 = t + i * 256;
                int dr = f4 >> 3, cq = f4 & 7;
                cp_async16(dstb + (dr * PSTR + cq * 4) * 4,
                           src + (size_t)dr * Nn + cq * 4);
            }
            CP_COMMIT();
            CP_WAIT(1);
        } else {
            CP_WAIT(0);
        }
        __syncthreads();

        // MMA over this 32-k chunk
        #pragma unroll
        for (int k8 = 0; k8 < 4; k8++) {
            const int kb = k8 * 8;
            uint32_t af[4][4];
            #pragma unroll
            for (int mt = 0; mt < 4; mt++) {
                const float* pa = sPb + (mbase + mt * 16 + g) * PSTR + kb + tig;
                af[mt][0] = __float_as_uint(pa[0]);
                af[mt][2] = __float_as_uint(pa[4]);
                af[mt][1] = __float_as_uint(pa[8 * PSTR]);
                af[mt][3] = __float_as_uint(pa[8 * PSTR + 4]);
            }
            uint32_t bf[8][2];
            #pragma unroll
            for (int nt = 0; nt < 8; nt++) {
                const float* pb = sFb + (nbase + nt * 8 + g) * PSTR + kb + tig;
                bf[nt][0] = __float_as_uint(pb[0]);
                bf[nt][1] = __float_as_uint(pb[4]);
            }
            #pragma unroll
            for (int mt = 0; mt < 4; mt++)
                #pragma unroll
                for (int nt = 0; nt < 8; nt++)
                    mma_tf32(acc[mt][nt], af[mt][0], af[mt][1], af[mt][2], af[mt][3],
                             bf[nt][0], bf[nt][1]);
        }
        __syncthreads();
    }

    // epilogue: write h_prime
    #pragma unroll
    for (int mt = 0; mt < 4; mt++) {
        int r0 = rowbase + mbase + mt * 16 + g;
        #pragma unroll
        for (int nt = 0; nt < 8; nt++) {
            int col = nbase + nt * 8 + 2 * tig;
            *(float2*)&g_hp[(size_t)r0 * Dd + col] =
                make_float2(acc[mt][nt][0], acc[mt][nt][1]);
            *(float2*)&g_hp[(size_t)(r0 + 8) * Dd + col] =
                make_float2(acc[mt][nt][2], acc[mt][nt][3]);
        }
    }
}

// ---------------- K4: out = elu(h_prime @ W) via warp-level tf32 MMA ----------------
// CTA 128 x 256, K = 256 in 8 chunks of 32.
#define KO_OFF_A 0
#define KO_A_SZ  (128 * PSTR)               // 4608 floats
#define KO_OFF_W KO_A_SZ
#define KO_W_SZ  (256 * PSTR)               // 9216 floats
#define KO_SMEM_BYTES ((KO_A_SZ + KO_W_SZ) * 4)   // 55296

__global__ void __launch_bounds__(256, 1) k_out_mma(const float* __restrict__ W,
                                                    float* __restrict__ out) {
    extern __shared__ float s[];
    const int t = threadIdx.x;
    const int wid = t >> 5, lane = t & 31;
    const int g = lane >> 2, tig = lane & 3;
    const int rowbase = blockIdx.x * 128;
    const int mbase = (wid & 1) * 64;
    const int nbase = (wid >> 1) * 64;
    float* sA = s + KO_OFF_A;
    float* sW = s + KO_OFF_W;

    float acc[4][8][4];
    #pragma unroll
    for (int mt = 0; mt < 4; mt++)
        #pragma unroll
        for (int nt = 0; nt < 8; nt++)
            #pragma unroll
            for (int r = 0; r < 4; r++) acc[mt][nt][r] = 0.f;

    for (int k0 = 0; k0 < Dd; k0 += 32) {
        // stage A chunk (tf32-rounded)
        #pragma unroll
        for (int i = 0; i < 4; i++) {
            int f4 = t + i * 256;
            int jr = f4 >> 3, kc = (f4 & 7) * 4;
            float4 v = *(const float4*)(g_hp + (size_t)(rowbase + jr) * Dd + k0 + kc);
            *(float4*)&sA[jr * PSTR + kc] = make_float4(
                to_tf32(v.x), to_tf32(v.y), to_tf32(v.z), to_tf32(v.w));
        }
        // stage W^T chunk: sW[n][k] = W[k0+k][n], tf32-rounded
        {
            int kk = t >> 3;
            int n0 = (t & 7) * 32;
            #pragma unroll
            for (int q = 0; q < 8; q++) {
                float4 w = *(const float4*)(W + (size_t)(k0 + kk) * Dd + n0 + q * 4);
                sW[(n0 + q * 4 + 0) * PSTR + kk] = to_tf32(w.x);
                sW[(n0 + q * 4 + 1) * PSTR + kk] = to_tf32(w.y);
                sW[(n0 + q * 4 + 2) * PSTR + kk] = to_tf32(w.z);
                sW[(n0 + q * 4 + 3) * PSTR + kk] = to_tf32(w.w);
            }
        }
        __syncthreads();

        #pragma unroll
        for (int k8 = 0; k8 < 4; k8++) {
            const int kb = k8 * 8;
            uint32_t af[4][4];
            #pragma unroll
            for (int mt = 0; mt < 4; mt++) {
                const float* pa = sA + (mbase + mt * 16 + g) * PSTR + kb + tig;
                af[mt][0] = __float_as_uint(pa[0]);
                af[mt][2] = __float_as_uint(pa[4]);
                af[mt][1] = __float_as_uint(pa[8 * PSTR]);
                af[mt][3] = __float_as_uint(pa[8 * PSTR + 4]);
            }
            uint32_t bf[8][2];
            #pragma unroll
            for (int nt = 0; nt < 8; nt++) {
                const float* pb = sW + (nbase + nt * 8 + g) * PSTR + kb + tig;
                bf[nt][0] = __float_as_uint(pb[0]);
                bf[nt][1] = __float_as_uint(pb[4]);
            }
            #pragma unroll
            for (int mt = 0; mt < 4; mt++)
                #pragma unroll
                for (int nt = 0; nt < 8; nt++)
                    mma_tf32(acc[mt][nt], af[mt][0], af[mt][1], af[mt][2], af[mt][3],
                             bf[nt][0], bf[nt][1]);
        }
        __syncthreads();
    }

    // epilogue: ELU + store
    #pragma unroll
    for (int mt = 0; mt < 4; mt++) {
        int r0 = rowbase + mbase + mt * 16 + g;
        #pragma unroll
        for (int nt = 0; nt < 8; nt++) {
            int col = nbase + nt * 8 + 2 * tig;
            float v0 = acc[mt][nt][0], v1 = acc[mt][nt][1];
            float v2 = acc[mt][nt][2], v3 = acc[mt][nt][3];
            v0 = v0 > 0.f ? v0 : expm1f(v0);
            v1 = v1 > 0.f ? v1 : expm1f(v1);
            v2 = v2 > 0.f ? v2 : expm1f(v2);
            v3 = v3 > 0.f ? v3 : expm1f(v3);
            *(float2*)&out[(size_t)r0 * Dd + col] = make_float2(v0, v1);
            *(float2*)&out[(size_t)(r0 + 8) * Dd + col] = make_float2(v2, v3);
        }
    }
}

// ---------------- launch ----------------
extern "C" void kernel_launch(void* const* d_in, const int* in_sizes, int n_in,
                              void* d_out, int out_size) {
    const float* feat = (const float*)d_in[0];
    const int*   adj  = (const int*)d_in[1];
    const float* W    = (const float*)d_in[2];
    const float* a1   = (const float*)d_in[3];
    const float* a2   = (const float*)d_in[4];
    float* out = (float*)d_out;

    cudaFuncSetAttribute(k_attn_mma, cudaFuncAttributeMaxDynamicSharedMemorySize, AT_SMEM_BYTES);
    cudaFuncSetAttribute(k_out_mma, cudaFuncAttributeMaxDynamicSharedMemorySize, KO_SMEM_BYTES);
    cudaFuncSetAttribute(k_rowstats, cudaFuncAttributeMaxDynamicSharedMemorySize, 3 * Nn * 4);

    k_u<<<1, 256>>>(W, a1, a2);
    k_axay<<<ROWS / 8, 256>>>(feat);
    k_exp<<<ROWS / 256, 256>>>();
    k_transpose<<<dim3(Nn / 32, Dd / 32, Bz), dim3(32, 8)>>>(feat);
    k_rowstats<<<ROWS / 8, 256, 3 * Nn * 4>>>(adj);
    k_attn_mma<<<ROWS / 128, 256, AT_SMEM_BYTES>>>();
    k_out_mma<<<ROWS / 128, 256, KO_SMEM_BYTES>>>(W, out);
}

// round 4
// speedup vs baseline: 3.0842x; 1.4455x over previous
#include <cuda_runtime.h>
#include <cuda_bf16.h>
#include <cstdint>

// Problem constants (B=4, N=4096, D=256)
#define Bz 4
#define Nn 4096
#define Dd 256
#define ROWS (Bz * Nn)          // 16384
#define ALPHA_F 0.2f

// ---------------- device scratch (static, allocation-free) ----------------
__device__ float g_u1[Dd], g_u2[Dd];
__device__ float g_Ax[ROWS], g_Ay[ROWS];
__device__ float g_E1[ROWS], g_E2[ROWS];                // exp(Ax), exp(0.2 Ax)
__device__ float g_F1[ROWS], g_F2[ROWS], g_T[ROWS];     // per-row softmax factors
__device__ unsigned g_bits[(size_t)ROWS * (Nn / 32)];   // 8 MB adjacency bitmask
__device__ float g_hp[(size_t)ROWS * Dd];               // 16 MB h_prime
__device__ float g_FT[(size_t)Bz * Dd * Nn];            // 16 MB feat^T (tf32-rounded)

// ---------------- helpers ----------------
__device__ __forceinline__ uint32_t smem_u32(const void* p) {
    uint32_t a;
    asm("{ .reg .u64 t; cvta.to.shared.u64 t, %1; cvt.u32.u64 %0, t; }" : "=r"(a) : "l"(p));
    return a;
}
__device__ __forceinline__ float to_tf32(float x) {
    uint32_t u;
    asm("cvt.rna.tf32.f32 %0, %1;" : "=r"(u) : "f"(x));
    return __uint_as_float(u);
}
__device__ __forceinline__ void cp_async16(uint32_t dst, const void* src) {
    asm volatile("cp.async.cg.shared.global [%0], [%1], 16;" :: "r"(dst), "l"(src));
}
#define CP_COMMIT()  asm volatile("cp.async.commit_group;" ::: "memory")
#define CP_WAIT(n)   asm volatile("cp.async.wait_group %0;" :: "n"(n) : "memory")

// m16n8k8 tf32 warp MMA
__device__ __forceinline__ void mma_tf32(float* c, uint32_t a0, uint32_t a1,
                                         uint32_t a2, uint32_t a3,
                                         uint32_t b0, uint32_t b1) {
    asm volatile(
        "mma.sync.aligned.m16n8k8.row.col.f32.tf32.tf32.f32 "
        "{%0,%1,%2,%3}, {%4,%5,%6,%7}, {%8,%9}, {%0,%1,%2,%3};"
        : "+f"(c[0]), "+f"(c[1]), "+f"(c[2]), "+f"(c[3])
        : "r"(a0), "r"(a1), "r"(a2), "r"(a3), "r"(b0), "r"(b1));
}

// ---------------- K0: u1 = W @ a1, u2 = W @ a2 ----------------
__global__ void k_u(const float* __restrict__ W, const float* __restrict__ a1,
                    const float* __restrict__ a2) {
    __shared__ float s1[Dd], s2[Dd];
    int t = threadIdx.x;
    s1[t] = a1[t]; s2[t] = a2[t];
    __syncthreads();
    const float* row = W + (size_t)t * Dd;
    float acc1 = 0.f, acc2 = 0.f;
    #pragma unroll 8
    for (int d = 0; d < Dd; d++) { float w = row[d]; acc1 += w * s1[d]; acc2 += w * s2[d]; }
    g_u1[t] = acc1; g_u2[t] = acc2;
}

// ---------------- K1: Ax, Ay ----------------
__global__ void __launch_bounds__(256) k_axay(const float* __restrict__ feat) {
    int row = blockIdx.x * 8 + (threadIdx.x >> 5);
    int lane = threadIdx.x & 31;
    const float* f = feat + (size_t)row * Dd;
    float a = 0.f, b = 0.f;
    #pragma unroll
    for (int k = lane; k < Dd; k += 32) { float v = f[k]; a += v * g_u1[k]; b += v * g_u2[k]; }
    #pragma unroll
    for (int o = 16; o; o >>= 1) {
        a += __shfl_xor_sync(0xffffffffu, a, o);
        b += __shfl_xor_sync(0xffffffffu, b, o);
    }
    if (lane == 0) { g_Ax[row] = a; g_Ay[row] = b; }
}

// ---------------- K1b: E1/E2 ----------------
__global__ void k_exp() {
    int i = blockIdx.x * 256 + threadIdx.x;
    float a = g_Ax[i];
    g_E1[i] = expf(a);
    g_E2[i] = expf(ALPHA_F * a);
}

// ---------------- K1c: feat^T (tf32-rounded) ----------------
__global__ void k_transpose(const float* __restrict__ feat) {
    __shared__ float tile[32][33];
    int j0 = blockIdx.x * 32, d0 = blockIdx.y * 32, b = blockIdx.z;
    int tx = threadIdx.x, ty = threadIdx.y;
    const float* fb = feat + (size_t)b * Nn * Dd;
    #pragma unroll
    for (int r = 0; r < 4; r++)
        tile[ty + r * 8][tx] = fb[(size_t)(j0 + ty + r * 8) * Dd + d0 + tx];
    __syncthreads();
    float* ob = g_FT + (size_t)b * Dd * Nn;
    #pragma unroll
    for (int r = 0; r < 4; r++)
        ob[(size_t)(d0 + ty + r * 8) * Nn + j0 + tx] = to_tf32(tile[tx][ty + r * 8]);
}

// ---------------- K2: row stats + bitmask (conflict-free strided layout) ----------------
// Thread t owns j = q*1024 + t*4 + {0..3}: adj int4 coalesced, E1/E2 via LDS.128
// with lane-consecutive addresses (zero bank conflicts). max(masked Ax) is taken
// as log(max masked E1) (monotone equivalence).
__global__ void __launch_bounds__(256) k_rowstats(const int* __restrict__ adj) {
    __shared__ float sE1[Nn], sE2[Nn];
    __shared__ float srM[8], srS1[8], srS2[8];

    int rb = blockIdx.x * 8;
    int b  = rb >> 12;
    int t  = threadIdx.x;

    const float4* g1 = (const float4*)(g_E1 + (size_t)b * Nn);
    const float4* g2 = (const float4*)(g_E2 + (size_t)b * Nn);
    #pragma unroll
    for (int i = 0; i < 4; i++) {
        ((float4*)sE1)[t + i * 256] = g1[t + i * 256];
        ((float4*)sE2)[t + i * 256] = g2[t + i * 256];
    }
    __syncthreads();

    for (int rr = 0; rr < 8; rr++) {
        int row = rb + rr;
        float Ay = g_Ay[row];
        float T  = __expf(-Ay);
        const int4* arow = (const int4*)(adj + (size_t)row * Nn);

        float mxE = 0.f, S1 = 0.f, S2 = 0.f;
        #pragma unroll
        for (int q = 0; q < 4; q++) {
            int4 a4 = arow[q * 256 + t];
            float4 e1v = ((const float4*)sE1)[q * 256 + t];
            float4 e2v = ((const float4*)sE2)[q * 256 + t];
            float e1a[4] = { e1v.x, e1v.y, e1v.z, e1v.w };
            float e2a[4] = { e2v.x, e2v.y, e2v.z, e2v.w };
            int av[4] = { a4.x, a4.y, a4.z, a4.w };
            unsigned nib = 0u;
            #pragma unroll
            for (int r = 0; r < 4; r++) {
                if (av[r] > 0) {
                    nib |= 1u << r;
                    float e1 = e1a[r];
                    mxE = fmaxf(mxE, e1);
                    if (e1 > T) S1 += e1; else S2 += e2a[r];
                }
            }
            // assemble 32-bit mask word from 8 lanes' nibbles
            unsigned v = nib << ((t & 7) * 4);
            v |= __shfl_xor_sync(0xffffffffu, v, 1);
            v |= __shfl_xor_sync(0xffffffffu, v, 2);
            v |= __shfl_xor_sync(0xffffffffu, v, 4);
            if ((t & 7) == 0)
                g_bits[(size_t)row * (Nn / 32) + q * 32 + (t >> 3)] = v;
        }

        #pragma unroll
        for (int o = 16; o; o >>= 1) {
            mxE = fmaxf(mxE, __shfl_xor_sync(0xffffffffu, mxE, o));
            S1 += __shfl_xor_sync(0xffffffffu, S1, o);
            S2 += __shfl_xor_sync(0xffffffffu, S2, o);
        }
        if ((t & 31) == 0) { int w = t >> 5; srM[w] = mxE; srS1[w] = S1; srS2[w] = S2; }
        __syncthreads();
        if (t == 0) {
            float M = srM[0], s1 = srS1[0], s2 = srS2[0];
            #pragma unroll
            for (int w = 1; w < 8; w++) {
                M = fmaxf(M, srM[w]); s1 += srS1[w]; s2 += srS2[w];
            }
            float m0 = Ay + logf(M);
            float m  = m0 > 0.f ? m0 : ALPHA_F * m0;   // leakyrelu(max) = max(leakyrelu)
            float eP = __expf(Ay - m);
            float eN = __expf(ALPHA_F * Ay - m);
            float invs = 1.f / (eP * s1 + eN * s2);
            g_F1[row] = eP * invs;
            g_F2[row] = eN * invs;
            g_T[row]  = T;
        }
        __syncthreads();
    }
}

// ---------------- K3: h_prime = P @ feat via warp tf32 MMA ----------------
// CTA tile 128 rows x 128 d-cols (grid 2 x 128 = 256 CTAs, 2 CTAs/SM).
// 8 warps, warp tile 64x32. K = 4096 in chunks of 32, double-buffered.
#define PSTR 36
#define OFF_E1 0
#define OFF_E2 4096
#define OFF_P  8192
#define P_SZ   (128 * PSTR)                 // 4608 floats
#define OFF_F  (OFF_P + 2 * P_SZ)           // 17408
#define F_SZ   (128 * PSTR)                 // 4608 floats
#define AT_SMEM_BYTES ((OFF_F + 2 * F_SZ) * 4)   // 106496

__global__ void __launch_bounds__(256, 2) k_attn_mma() {
    extern __shared__ float s[];
    const uint32_t sb = smem_u32(s);
    const int t = threadIdx.x;
    const int wid = t >> 5, lane = t & 31;
    const int g = lane >> 2, tig = lane & 3;
    const int dtile = blockIdx.x;
    const int rowbase = blockIdx.y * 128;
    const int b = rowbase >> 12;            // 4096 % 128 == 0
    const float* FTb = g_FT + (size_t)b * Dd * Nn + (size_t)dtile * 128 * Nn;

    // stage E1/E2 for this batch
    {
        const float4* s1 = (const float4*)(g_E1 + (size_t)b * Nn);
        const float4* s2 = (const float4*)(g_E2 + (size_t)b * Nn);
        #pragma unroll
        for (int i = 0; i < 4; i++) {
            ((float4*)(s + OFF_E1))[t + i * 256] = s1[t + i * 256];
            ((float4*)(s + OFF_E2))[t + i * 256] = s2[t + i * 256];
        }
    }
    const int ip = t >> 1, jh = t & 1;      // P-build role: row ip, 16-j half jh
    const int grow = rowbase + ip;
    const float F1 = g_F1[grow], F2 = g_F2[grow], T = g_T[grow];
    const unsigned* bitsrow = g_bits + (size_t)grow * (Nn / 32);
    const float* sE1 = s + OFF_E1;
    const float* sE2 = s + OFF_E2;
    __syncthreads();

    // prefetch F chunk 0 into buffer 0 (128 d-rows x 32 j)
    {
        #pragma unroll
        for (int i = 0; i < 4; i++) {
            int f4 = t + i * 256;
            int dr = f4 >> 3, cq = f4 & 7;
            cp_async16(sb + (OFF_F + dr * PSTR + cq * 4) * 4,
                       FTb + (size_t)dr * Nn + cq * 4);
        }
        CP_COMMIT();
    }

    const int mbase = (wid & 1) * 64;
    const int nbase = (wid >> 1) * 32;
    float acc[4][4][4];
    #pragma unroll
    for (int mt = 0; mt < 4; mt++)
        #pragma unroll
        for (int nt = 0; nt < 4; nt++)
            #pragma unroll
            for (int r = 0; r < 4; r++) acc[mt][nt][r] = 0.f;

    for (int c = 0; c < Nn / 32; c++) {
        const int buf = c & 1;
        float* sPb = s + OFF_P + buf * P_SZ;
        float* sFb = s + OFF_F + buf * F_SZ;
        const int j0 = c * 32;

        // build P(c): row ip, 16 j-values of half jh
        {
            unsigned wb = bitsrow[c];
            unsigned half = jh ? (wb >> 16) : (wb & 0xffffu);
            const int kb = jh * 16;
            #pragma unroll
            for (int q = 0; q < 4; q++) {
                float v[4];
                #pragma unroll
                for (int r = 0; r < 4; r++) {
                    int jj = q * 4 + r;
                    float e1 = sE1[j0 + kb + jj];
                    float p = (e1 > T) ? e1 * F1 : sE2[j0 + kb + jj] * F2;
                    v[r] = to_tf32(((half >> jj) & 1u) ? p : 0.f);
                }
                *(float4*)&sPb[ip * PSTR + kb + q * 4] =
                    make_float4(v[0], v[1], v[2], v[3]);
            }
        }
        // prefetch F(c+1)
        if (c + 1 < Nn / 32) {
            uint32_t dstb = sb + (OFF_F + (1 - buf) * F_SZ) * 4;
            const float* src = FTb + j0 + 32;
            #pragma unroll
            for (int i = 0; i < 4; i++) {
                int f4 = t + i * 256;
                int dr = f4 >> 3, cq = f4 & 7;
                cp_async16(dstb + (dr * PSTR + cq * 4) * 4,
                           src + (size_t)dr * Nn + cq * 4);
            }
            CP_COMMIT();
            CP_WAIT(1);
        } else {
            CP_WAIT(0);
        }
        __syncthreads();

        #pragma unroll
        for (int k8 = 0; k8 < 4; k8++) {
            const int kb = k8 * 8;
            uint32_t af[4][4];
            #pragma unroll
            for (int mt = 0; mt < 4; mt++) {
                const float* pa = sPb + (mbase + mt * 16 + g) * PSTR + kb + tig;
                af[mt][0] = __float_as_uint(pa[0]);
                af[mt][2] = __float_as_uint(pa[4]);
                af[mt][1] = __float_as_uint(pa[8 * PSTR]);
                af[mt][3] = __float_as_uint(pa[8 * PSTR + 4]);
            }
            uint32_t bf[4][2];
            #pragma unroll
            for (int nt = 0; nt < 4; nt++) {
                const float* pb = sFb + (nbase + nt * 8 + g) * PSTR + kb + tig;
                bf[nt][0] = __float_as_uint(pb[0]);
                bf[nt][1] = __float_as_uint(pb[4]);
            }
            #pragma unroll
            for (int mt = 0; mt < 4; mt++)
                #pragma unroll
                for (int nt = 0; nt < 4; nt++)
                    mma_tf32(acc[mt][nt], af[mt][0], af[mt][1], af[mt][2], af[mt][3],
                             bf[nt][0], bf[nt][1]);
        }
        __syncthreads();
    }

    // epilogue: write h_prime
    #pragma unroll
    for (int mt = 0; mt < 4; mt++) {
        int r0 = rowbase + mbase + mt * 16 + g;
        #pragma unroll
        for (int nt = 0; nt < 4; nt++) {
            int col = dtile * 128 + nbase + nt * 8 + 2 * tig;
            *(float2*)&g_hp[(size_t)r0 * Dd + col] =
                make_float2(acc[mt][nt][0], acc[mt][nt][1]);
            *(float2*)&g_hp[(size_t)(r0 + 8) * Dd + col] =
                make_float2(acc[mt][nt][2], acc[mt][nt][3]);
        }
    }
}

// ---------------- K4: out = elu(h_prime @ W) via warp tf32 MMA ----------------
#define KO_OFF_A 0
#define KO_A_SZ  (128 * PSTR)               // 4608 floats
#define KO_OFF_W KO_A_SZ
#define KO_W_SZ  (256 * PSTR)               // 9216 floats
#define KO_SMEM_BYTES ((KO_A_SZ + KO_W_SZ) * 4)   // 55296

__global__ void __launch_bounds__(256, 1) k_out_mma(const float* __restrict__ W,
                                                    float* __restrict__ out) {
    extern __shared__ float s[];
    const int t = threadIdx.x;
    const int wid = t >> 5, lane = t & 31;
    const int g = lane >> 2, tig = lane & 3;
    const int rowbase = blockIdx.x * 128;
    const int mbase = (wid & 1) * 64;
    const int nbase = (wid >> 1) * 64;
    float* sA = s + KO_OFF_A;
    float* sW = s + KO_OFF_W;

    float acc[4][8][4];
    #pragma unroll
    for (int mt = 0; mt < 4; mt++)
        #pragma unroll
        for (int nt = 0; nt < 8; nt++)
            #pragma unroll
            for (int r = 0; r < 4; r++) acc[mt][nt][r] = 0.f;

    for (int k0 = 0; k0 < Dd; k0 += 32) {
        #pragma unroll
        for (int i = 0; i < 4; i++) {
            int f4 = t + i * 256;
            int jr = f4 >> 3, kc = (f4 & 7) * 4;
            float4 v = *(const float4*)(g_hp + (size_t)(rowbase + jr) * Dd + k0 + kc);
            *(float4*)&sA[jr * PSTR + kc] = make_float4(
                to_tf32(v.x), to_tf32(v.y), to_tf32(v.z), to_tf32(v.w));
        }
        {
            int kk = t >> 3;
            int n0 = (t & 7) * 32;
            #pragma unroll
            for (int q = 0; q < 8; q++) {
                float4 w = *(const float4*)(W + (size_t)(k0 + kk) * Dd + n0 + q * 4);
                sW[(n0 + q * 4 + 0) * PSTR + kk] = to_tf32(w.x);
                sW[(n0 + q * 4 + 1) * PSTR + kk] = to_tf32(w.y);
                sW[(n0 + q * 4 + 2) * PSTR + kk] = to_tf32(w.z);
                sW[(n0 + q * 4 + 3) * PSTR + kk] = to_tf32(w.w);
            }
        }
        __syncthreads();

        #pragma unroll
        for (int k8 = 0; k8 < 4; k8++) {
            const int kb = k8 * 8;
            uint32_t af[4][4];
            #pragma unroll
            for (int mt = 0; mt < 4; mt++) {
                const float* pa = sA + (mbase + mt * 16 + g) * PSTR + kb + tig;
                af[mt][0] = __float_as_uint(pa[0]);
                af[mt][2] = __float_as_uint(pa[4]);
                af[mt][1] = __float_as_uint(pa[8 * PSTR]);
                af[mt][3] = __float_as_uint(pa[8 * PSTR + 4]);
            }
            uint32_t bf[8][2];
            #pragma unroll
            for (int nt = 0; nt < 8; nt++) {
                const float* pb = sW + (nbase + nt * 8 + g) * PSTR + kb + tig;
                bf[nt][0] = __float_as_uint(pb[0]);
                bf[nt][1] = __float_as_uint(pb[4]);
            }
            #pragma unroll
            for (int mt = 0; mt < 4; mt++)
                #pragma unroll
                for (int nt = 0; nt < 8; nt++)
                    mma_tf32(acc[mt][nt], af[mt][0], af[mt][1], af[mt][2], af[mt][3],
                             bf[nt][0], bf[nt][1]);
        }
        __syncthreads();
    }

    #pragma unroll
    for (int mt = 0; mt < 4; mt++) {
        int r0 = rowbase + mbase + mt * 16 + g;
        #pragma unroll
        for (int nt = 0; nt < 8; nt++) {
            int col = nbase + nt * 8 + 2 * tig;
            float v0 = acc[mt][nt][0], v1 = acc[mt][nt][1];
            float v2 = acc[mt][nt][2], v3 = acc[mt][nt][3];
            v0 = v0 > 0.f ? v0 : expm1f(v0);
            v1 = v1 > 0.f ? v1 : expm1f(v1);
            v2 = v2 > 0.f ? v2 : expm1f(v2);
            v3 = v3 > 0.f ? v3 : expm1f(v3);
            *(float2*)&out[(size_t)r0 * Dd + col] = make_float2(v0, v1);
            *(float2*)&out[(size_t)(r0 + 8) * Dd + col] = make_float2(v2, v3);
        }
    }
}

// ---------------- launch ----------------
extern "C" void kernel_launch(void* const* d_in, const int* in_sizes, int n_in,
                              void* d_out, int out_size) {
    const float* feat = (const float*)d_in[0];
    const int*   adj  = (const int*)d_in[1];
    const float* W    = (const float*)d_in[2];
    const float* a1   = (const float*)d_in[3];
    const float* a2   = (const float*)d_in[4];
    float* out = (float*)d_out;

    cudaFuncSetAttribute(k_attn_mma, cudaFuncAttributeMaxDynamicSharedMemorySize, AT_SMEM_BYTES);
    cudaFuncSetAttribute(k_out_mma, cudaFuncAttributeMaxDynamicSharedMemorySize, KO_SMEM_BYTES);

    k_u<<<1, 256>>>(W, a1, a2);
    k_axay<<<ROWS / 8, 256>>>(feat);
    k_exp<<<ROWS / 256, 256>>>();
    k_transpose<<<dim3(Nn / 32, Dd / 32, Bz), dim3(32, 8)>>>(feat);
    k_rowstats<<<ROWS / 8, 256>>>(adj);
    k_attn_mma<<<dim3(2, ROWS / 128), 256, AT_SMEM_BYTES>>>();
    k_out_mma<<<ROWS / 128, 256, KO_SMEM_BYTES>>>(W, out);
}

// round 7
// speedup vs baseline: 4.0871x; 1.3252x over previous
#include <cuda_runtime.h>
#include <cuda_fp16.h>
#include <cuda_bf16.h>
#include <cstdint>

// Problem constants (B=4, N=4096, D=256)
#define Bz 4
#define Nn 4096
#define Dd 256
#define ROWS (Bz * Nn)          // 16384
#define ALPHA_F 0.2f

// ---------------- device scratch (static, allocation-free) ----------------
__device__ float g_u1[Dd], g_u2[Dd];
__device__ float g_Ax[ROWS], g_Ay[ROWS];
__device__ float g_E1[ROWS], g_E2[ROWS];                // exp(Ax), exp(0.2 Ax)
__device__ float g_F1[ROWS], g_F2[ROWS], g_T[ROWS];     // per-row softmax factors
__device__ unsigned g_bits[(size_t)ROWS * (Nn / 32)];   // 8 MB adjacency bitmask
__device__ float g_hp[(size_t)ROWS * Dd];               // 16 MB h_prime
__device__ __half g_FT[(size_t)Bz * Dd * Nn];           // 8 MB feat^T (fp16)

// ---------------- helpers ----------------
__device__ __forceinline__ uint32_t smem_u32(const void* p) {
    uint32_t a;
    asm("{ .reg .u64 t; cvta.to.shared.u64 t, %1; cvt.u32.u64 %0, t; }" : "=r"(a) : "l"(p));
    return a;
}
__device__ __forceinline__ float to_tf32(float x) {
    uint32_t u;
    asm("cvt.rna.tf32.f32 %0, %1;" : "=r"(u) : "f"(x));
    return __uint_as_float(u);
}
__device__ __forceinline__ uint32_t h2_as_u32(__half2 h) {
    uint32_t u;
    __builtin_memcpy(&u, &h, sizeof(u));
    return u;
}
__device__ __forceinline__ void cp_async16(uint32_t dst, const void* src) {
    asm volatile("cp.async.cg.shared.global [%0], [%1], 16;" :: "r"(dst), "l"(src));
}
#define CP_COMMIT()  asm volatile("cp.async.commit_group;" ::: "memory")
#define CP_WAIT(n)   asm volatile("cp.async.wait_group %0;" :: "n"(n) : "memory")

// m16n8k16 fp16 warp MMA, fp32 accumulate
__device__ __forceinline__ void mma_f16(float* c, uint32_t a0, uint32_t a1,
                                        uint32_t a2, uint32_t a3,
                                        uint32_t b0, uint32_t b1) {
    asm volatile(
        "mma.sync.aligned.m16n8k16.row.col.f32.f16.f16.f32 "
        "{%0,%1,%2,%3}, {%4,%5,%6,%7}, {%8,%9}, {%0,%1,%2,%3};"
        : "+f"(c[0]), "+f"(c[1]), "+f"(c[2]), "+f"(c[3])
        : "r"(a0), "r"(a1), "r"(a2), "r"(a3), "r"(b0), "r"(b1));
}
// m16n8k8 tf32 warp MMA (second GEMM keeps full 11-bit path on fp32 data)
__device__ __forceinline__ void mma_tf32(float* c, uint32_t a0, uint32_t a1,
                                         uint32_t a2, uint32_t a3,
                                         uint32_t b0, uint32_t b1) {
    asm volatile(
        "mma.sync.aligned.m16n8k8.row.col.f32.tf32.tf32.f32 "
        "{%0,%1,%2,%3}, {%4,%5,%6,%7}, {%8,%9}, {%0,%1,%2,%3};"
        : "+f"(c[0]), "+f"(c[1]), "+f"(c[2]), "+f"(c[3])
        : "r"(a0), "r"(a1), "r"(a2), "r"(a3), "r"(b0), "r"(b1));
}

// ---------------- K0: u1 = W @ a1, u2 = W @ a2 ----------------
__global__ void k_u(const float* __restrict__ W, const float* __restrict__ a1,
                    const float* __restrict__ a2) {
    __shared__ float s1[Dd], s2[Dd];
    int t = threadIdx.x;
    s1[t] = a1[t]; s2[t] = a2[t];
    __syncthreads();
    const float* row = W + (size_t)t * Dd;
    float acc1 = 0.f, acc2 = 0.f;
    #pragma unroll 8
    for (int d = 0; d < Dd; d++) { float w = row[d]; acc1 += w * s1[d]; acc2 += w * s2[d]; }
    g_u1[t] = acc1; g_u2[t] = acc2;
}

// ---------------- K1: Ax, Ay ----------------
__global__ void __launch_bounds__(256) k_axay(const float* __restrict__ feat) {
    int row = blockIdx.x * 8 + (threadIdx.x >> 5);
    int lane = threadIdx.x & 31;
    const float* f = feat + (size_t)row * Dd;
    float a = 0.f, b = 0.f;
    #pragma unroll
    for (int k = lane; k < Dd; k += 32) { float v = f[k]; a += v * g_u1[k]; b += v * g_u2[k]; }
    #pragma unroll
    for (int o = 16; o; o >>= 1) {
        a += __shfl_xor_sync(0xffffffffu, a, o);
        b += __shfl_xor_sync(0xffffffffu, b, o);
    }
    if (lane == 0) { g_Ax[row] = a; g_Ay[row] = b; }
}

// ---------------- K1b: E1/E2 ----------------
__global__ void k_exp() {
    int i = blockIdx.x * 256 + threadIdx.x;
    float a = g_Ax[i];
    g_E1[i] = expf(a);
    g_E2[i] = expf(ALPHA_F * a);
}

// ---------------- K1c: feat^T (fp16) ----------------
__global__ void k_transpose(const float* __restrict__ feat) {
    __shared__ float tile[32][33];
    int j0 = blockIdx.x * 32, d0 = blockIdx.y * 32, b = blockIdx.z;
    int tx = threadIdx.x, ty = threadIdx.y;
    const float* fb = feat + (size_t)b * Nn * Dd;
    #pragma unroll
    for (int r = 0; r < 4; r++)
        tile[ty + r * 8][tx] = fb[(size_t)(j0 + ty + r * 8) * Dd + d0 + tx];
    __syncthreads();
    __half* ob = g_FT + (size_t)b * Dd * Nn;
    #pragma unroll
    for (int r = 0; r < 4; r++)
        ob[(size_t)(d0 + ty + r * 8) * Nn + j0 + tx] = __float2half_rn(tile[tx][ty + r * 8]);
}

// ---------------- K2: row stats + bitmask (conflict-free strided layout) ----------------
__global__ void __launch_bounds__(256) k_rowstats(const int* __restrict__ adj) {
    __shared__ float sE1[Nn], sE2[Nn];
    __shared__ float srM[8], srS1[8], srS2[8];

    int rb = blockIdx.x * 8;
    int b  = rb >> 12;
    int t  = threadIdx.x;

    const float4* g1 = (const float4*)(g_E1 + (size_t)b * Nn);
    const float4* g2 = (const float4*)(g_E2 + (size_t)b * Nn);
    #pragma unroll
    for (int i = 0; i < 4; i++) {
        ((float4*)sE1)[t + i * 256] = g1[t + i * 256];
        ((float4*)sE2)[t + i * 256] = g2[t + i * 256];
    }
    __syncthreads();

    for (int rr = 0; rr < 8; rr++) {
        int row = rb + rr;
        float Ay = g_Ay[row];
        float T  = __expf(-Ay);
        const int4* arow = (const int4*)(adj + (size_t)row * Nn);

        float mxE = 0.f, S1 = 0.f, S2 = 0.f;
        #pragma unroll
        for (int q = 0; q < 4; q++) {
            int4 a4 = arow[q * 256 + t];
            float4 e1v = ((const float4*)sE1)[q * 256 + t];
            float4 e2v = ((const float4*)sE2)[q * 256 + t];
            float e1a[4] = { e1v.x, e1v.y, e1v.z, e1v.w };
            float e2a[4] = { e2v.x, e2v.y, e2v.z, e2v.w };
            int av[4] = { a4.x, a4.y, a4.z, a4.w };
            unsigned nib = 0u;
            #pragma unroll
            for (int r = 0; r < 4; r++) {
                if (av[r] > 0) {
                    nib |= 1u << r;
                    float e1 = e1a[r];
                    mxE = fmaxf(mxE, e1);
                    if (e1 > T) S1 += e1; else S2 += e2a[r];
                }
            }
            unsigned v = nib << ((t & 7) * 4);
            v |= __shfl_xor_sync(0xffffffffu, v, 1);
            v |= __shfl_xor_sync(0xffffffffu, v, 2);
            v |= __shfl_xor_sync(0xffffffffu, v, 4);
            if ((t & 7) == 0)
                g_bits[(size_t)row * (Nn / 32) + q * 32 + (t >> 3)] = v;
        }

        #pragma unroll
        for (int o = 16; o; o >>= 1) {
            mxE = fmaxf(mxE, __shfl_xor_sync(0xffffffffu, mxE, o));
            S1 += __shfl_xor_sync(0xffffffffu, S1, o);
            S2 += __shfl_xor_sync(0xffffffffu, S2, o);
        }
        if ((t & 31) == 0) { int w = t >> 5; srM[w] = mxE; srS1[w] = S1; srS2[w] = S2; }
        __syncthreads();
        if (t == 0) {
            float M = srM[0], s1 = srS1[0], s2 = srS2[0];
            #pragma unroll
            for (int w = 1; w < 8; w++) {
                M = fmaxf(M, srM[w]); s1 += srS1[w]; s2 += srS2[w];
            }
            float m0 = Ay + logf(M);
            float m  = m0 > 0.f ? m0 : ALPHA_F * m0;
            float eP = __expf(Ay - m);
            float eN = __expf(ALPHA_F * Ay - m);
            float invs = 1.f / (eP * s1 + eN * s2);
            g_F1[row] = eP * invs;
            g_F2[row] = eN * invs;
            g_T[row]  = T;
        }
        __syncthreads();
    }
}

// ---------------- K3: h_prime = P @ feat via fp16 m16n8k16 MMA ----------------
// CTA tile 128 rows x 128 d-cols, 8 warps (warp 64x32), K-chunks of 64, double-buffered.
// P built as packed half2 straight into SMEM; F (feat^T fp16) via cp.async.
// Row stride 72 halves (144 B) => fragment LDS bank-conflict-free.
#define HSTR 72
#define AB_E1 0
#define AB_E2 16384
#define AB_P  32768
#define PBUF_B (128 * HSTR * 2)             // 18432 B
#define AB_F  (AB_P + 2 * PBUF_B)           // 69632
#define AT_SMEM_BYTES (AB_F + 2 * PBUF_B)   // 106496

__global__ void __launch_bounds__(256, 2) k_attn_mma() {
    extern __shared__ char smc[];
    const uint32_t sb = smem_u32(smc);
    float* sE1 = (float*)(smc + AB_E1);
    float* sE2 = (float*)(smc + AB_E2);
    const int t = threadIdx.x;
    const int wid = t >> 5, lane = t & 31;
    const int g = lane >> 2, tig = lane & 3;
    const int dtile = blockIdx.x;
    const int rowbase = blockIdx.y * 128;
    const int b = rowbase >> 12;            // 4096 % 128 == 0
    const __half* FTb = g_FT + (size_t)b * Dd * Nn + (size_t)dtile * 128 * Nn;

    // stage E1/E2 for this batch
    {
        const float4* s1 = (const float4*)(g_E1 + (size_t)b * Nn);
        const float4* s2 = (const float4*)(g_E2 + (size_t)b * Nn);
        #pragma unroll
        for (int i = 0; i < 4; i++) {
            ((float4*)sE1)[t + i * 256] = s1[t + i * 256];
            ((float4*)sE2)[t + i * 256] = s2[t + i * 256];
        }
    }
    const int ip = t >> 1, jh = t & 1;      // P-build: row ip, 32-j half jh
    const int grow = rowbase + ip;
    const float F1 = g_F1[grow], F2 = g_F2[grow], T = g_T[grow];
    const unsigned* bitsrow = g_bits + (size_t)grow * (Nn / 32);
    __syncthreads();

    // prefetch F chunk 0 (128 d-rows x 64 j fp16 = 16 KB)
    {
        #pragma unroll
        for (int i = 0; i < 4; i++) {
            int f = t + i * 256;
            int dr = f >> 3, cq = f & 7;
            cp_async16(sb + AB_F + dr * 144 + cq * 16,
                       FTb + (size_t)dr * Nn + cq * 8);
        }
        CP_COMMIT();
    }

    const int mbase = (wid & 1) * 64;
    const int nbase = (wid >> 1) * 32;
    float acc[4][4][4];
    #pragma unroll
    for (int mt = 0; mt < 4; mt++)
        #pragma unroll
        for (int nt = 0; nt < 4; nt++)
            #pragma unroll
            for (int r = 0; r < 4; r++) acc[mt][nt][r] = 0.f;

    const int NCH = Nn / 64;
    for (int c = 0; c < NCH; c++) {
        const int buf = c & 1;
        char* Pb = smc + AB_P + buf * PBUF_B;
        const uint32_t* sPw = (const uint32_t*)(smc + AB_P + buf * PBUF_B);
        const uint32_t* sFw = (const uint32_t*)(smc + AB_F + buf * PBUF_B);
        const int j0 = c * 64;

        // prefetch F(c+1)
        if (c + 1 < NCH) {
            uint32_t dstb = sb + AB_F + (1 - buf) * PBUF_B;
            const __half* src = FTb + j0 + 64;
            #pragma unroll
            for (int i = 0; i < 4; i++) {
                int f = t + i * 256;
                int dr = f >> 3, cq = f & 7;
                cp_async16(dstb + dr * 144 + cq * 16,
                           src + (size_t)dr * Nn + cq * 8);
            }
            CP_COMMIT();
        }

        // build P(c): row ip, 32 j of half jh, packed fp16
        {
            unsigned wb = bitsrow[2 * c + jh];
            const float* e1p = sE1 + j0 + jh * 32;
            const float* e2p = sE2 + j0 + jh * 32;
            #pragma unroll
            for (int q = 0; q < 4; q++) {
                __half2 h[4];
                #pragma unroll
                for (int d = 0; d < 4; d++) {
                    int jj0 = q * 8 + d * 2;
                    float e1a = e1p[jj0],     e2a = e2p[jj0];
                    float e1b = e1p[jj0 + 1], e2b = e2p[jj0 + 1];
                    float pa = (e1a > T) ? e1a * F1 : e2a * F2;
                    float pb = (e1b > T) ? e1b * F1 : e2b * F2;
                    pa = ((wb >> jj0) & 1u) ? pa : 0.f;
                    pb = ((wb >> (jj0 + 1)) & 1u) ? pb : 0.f;
                    h[d] = __floats2half2_rn(pa, pb);
                }
                *(uint4*)(Pb + ip * 144 + jh * 64 + q * 16) =
                    make_uint4(h2_as_u32(h[0]), h2_as_u32(h[1]),
                               h2_as_u32(h[2]), h2_as_u32(h[3]));
            }
        }

        if (c + 1 < NCH) { CP_WAIT(1); } else { CP_WAIT(0); }
        __syncthreads();

        // MMA: 4 k16 steps over this K64 chunk
        #pragma unroll
        for (int k16 = 0; k16 < 4; k16++) {
            const int kw = k16 * 8 + tig;        // uint (half2) offset within row
            uint32_t af[4][4];
            #pragma unroll
            for (int mt = 0; mt < 4; mt++) {
                int r0 = (mbase + mt * 16 + g) * 36 + kw;
                af[mt][0] = sPw[r0];
                af[mt][2] = sPw[r0 + 4];
                af[mt][1] = sPw[r0 + 8 * 36];
                af[mt][3] = sPw[r0 + 8 * 36 + 4];
            }
            uint32_t bf[4][2];
            #pragma unroll
            for (int nt = 0; nt < 4; nt++) {
                int n0 = (nbase + nt * 8 + g) * 36 + kw;
                bf[nt][0] = sFw[n0];
                bf[nt][1] = sFw[n0 + 4];
            }
            #pragma unroll
            for (int mt = 0; mt < 4; mt++)
                #pragma unroll
                for (int nt = 0; nt < 4; nt++)
                    mma_f16(acc[mt][nt], af[mt][0], af[mt][1], af[mt][2], af[mt][3],
                            bf[nt][0], bf[nt][1]);
        }
        __syncthreads();
    }

    // epilogue: write h_prime (fp32)
    #pragma unroll
    for (int mt = 0; mt < 4; mt++) {
        int r0 = rowbase + mbase + mt * 16 + g;
        #pragma unroll
        for (int nt = 0; nt < 4; nt++) {
            int col = dtile * 128 + nbase + nt * 8 + 2 * tig;
            *(float2*)&g_hp[(size_t)r0 * Dd + col] =
                make_float2(acc[mt][nt][0], acc[mt][nt][1]);
            *(float2*)&g_hp[(size_t)(r0 + 8) * Dd + col] =
                make_float2(acc[mt][nt][2], acc[mt][nt][3]);
        }
    }
}

// ---------------- K4: out = elu(h_prime @ W) via warp tf32 MMA ----------------
#define PSTR 36
#define KO_A_SZ  (128 * PSTR)
#define KO_W_SZ  (256 * PSTR)
#define KO_SMEM_BYTES ((KO_A_SZ + KO_W_SZ) * 4)   // 55296

__global__ void __launch_bounds__(256, 1) k_out_mma(const float* __restrict__ W,
                                                    float* __restrict__ out) {
    extern __shared__ float s[];
    const int t = threadIdx.x;
    const int wid = t >> 5, lane = t & 31;
    const int g = lane >> 2, tig = lane & 3;
    const int rowbase = blockIdx.x * 128;
    const int mbase = (wid & 1) * 64;
    const int nbase = (wid >> 1) * 64;
    float* sA = s;
    float* sW = s + KO_A_SZ;

    float acc[4][8][4];
    #pragma unroll
    for (int mt = 0; mt < 4; mt++)
        #pragma unroll
        for (int nt = 0; nt < 8; nt++)
            #pragma unroll
            for (int r = 0; r < 4; r++) acc[mt][nt][r] = 0.f;

    for (int k0 = 0; k0 < Dd; k0 += 32) {
        #pragma unroll
        for (int i = 0; i < 4; i++) {
            int f4 = t + i * 256;
            int jr = f4 >> 3, kc = (f4 & 7) * 4;
            float4 v = *(const float4*)(g_hp + (size_t)(rowbase + jr) * Dd + k0 + kc);
            *(float4*)&sA[jr * PSTR + kc] = make_float4(
                to_tf32(v.x), to_tf32(v.y), to_tf32(v.z), to_tf32(v.w));
        }
        {
            int kk = t >> 3;
            int n0 = (t & 7) * 32;
            #pragma unroll
            for (int q = 0; q < 8; q++) {
                float4 w = *(const float4*)(W + (size_t)(k0 + kk) * Dd + n0 + q * 4);
                sW[(n0 + q * 4 + 0) * PSTR + kk] = to_tf32(w.x);
                sW[(n0 + q * 4 + 1) * PSTR + kk] = to_tf32(w.y);
                sW[(n0 + q * 4 + 2) * PSTR + kk] = to_tf32(w.z);
                sW[(n0 + q * 4 + 3) * PSTR + kk] = to_tf32(w.w);
            }
        }
        __syncthreads();

        #pragma unroll
        for (int k8 = 0; k8 < 4; k8++) {
            const int kb = k8 * 8;
            uint32_t af[4][4];
            #pragma unroll
            for (int mt = 0; mt < 4; mt++) {
                const float* pa = sA + (mbase + mt * 16 + g) * PSTR + kb + tig;
                af[mt][0] = __float_as_uint(pa[0]);
                af[mt][2] = __float_as_uint(pa[4]);
                af[mt][1] = __float_as_uint(pa[8 * PSTR]);
                af[mt][3] = __float_as_uint(pa[8 * PSTR + 4]);
            }
            uint32_t bf[8][2];
            #pragma unroll
            for (int nt = 0; nt < 8; nt++) {
                const float* pb = sW + (nbase + nt * 8 + g) * PSTR + kb + tig;
                bf[nt][0] = __float_as_uint(pb[0]);
                bf[nt][1] = __float_as_uint(pb[4]);
            }
            #pragma unroll
            for (int mt = 0; mt < 4; mt++)
                #pragma unroll
                for (int nt = 0; nt < 8; nt++)
                    mma_tf32(acc[mt][nt], af[mt][0], af[mt][1], af[mt][2], af[mt][3],
                             bf[nt][0], bf[nt][1]);
        }
        __syncthreads();
    }

    #pragma unroll
    for (int mt = 0; mt < 4; mt++) {
        int r0 = rowbase + mbase + mt * 16 + g;
        #pragma unroll
        for (int nt = 0; nt < 8; nt++) {
            int col = nbase + nt * 8 + 2 * tig;
            float v0 = acc[mt][nt][0], v1 = acc[mt][nt][1];
            float v2 = acc[mt][nt][2], v3 = acc[mt][nt][3];
            v0 = v0 > 0.f ? v0 : expm1f(v0);
            v1 = v1 > 0.f ? v1 : expm1f(v1);
            v2 = v2 > 0.f ? v2 : expm1f(v2);
            v3 = v3 > 0.f ? v3 : expm1f(v3);
            *(float2*)&out[(size_t)r0 * Dd + col] = make_float2(v0, v1);
            *(float2*)&out[(size_t)(r0 + 8) * Dd + col] = make_float2(v2, v3);
        }
    }
}

// ---------------- launch ----------------
extern "C" void kernel_launch(void* const* d_in, const int* in_sizes, int n_in,
                              void* d_out, int out_size) {
    const float* feat = (const float*)d_in[0];
    const int*   adj  = (const int*)d_in[1];
    const float* W    = (const float*)d_in[2];
    const float* a1   = (const float*)d_in[3];
    const float* a2   = (const float*)d_in[4];
    float* out = (float*)d_out;

    cudaFuncSetAttribute(k_attn_mma, cudaFuncAttributeMaxDynamicSharedMemorySize, AT_SMEM_BYTES);
    cudaFuncSetAttribute(k_out_mma, cudaFuncAttributeMaxDynamicSharedMemorySize, KO_SMEM_BYTES);

    k_u<<<1, 256>>>(W, a1, a2);
    k_axay<<<ROWS / 8, 256>>>(feat);
    k_exp<<<ROWS / 256, 256>>>();
    k_transpose<<<dim3(Nn / 32, Dd / 32, Bz), dim3(32, 8)>>>(feat);
    k_rowstats<<<ROWS / 8, 256>>>(adj);
    k_attn_mma<<<dim3(2, ROWS / 128), 256, AT_SMEM_BYTES>>>();
    k_out_mma<<<ROWS / 128, 256, KO_SMEM_BYTES>>>(W, out);
}

// round 9
// speedup vs baseline: 4.4324x; 1.0845x over previous
#include <cuda_runtime.h>
#include <cuda_fp16.h>
#include <cstdint>

// Problem constants (B=4, N=4096, D=256)
#define Bz 4
#define Nn 4096
#define Dd 256
#define ROWS (Bz * Nn)          // 16384
#define ALPHA_F 0.2f

// ---------------- device scratch (static, allocation-free) ----------------
__device__ float g_u1[Dd], g_u2[Dd];
__device__ float g_Ax[ROWS], g_Ay[ROWS];
__device__ float g_mb[Bz];                              // per-batch max Ax
__device__ unsigned g_G[ROWS];                          // packed half2 (G1,G2), batch-max normalized
__device__ float g_F1[ROWS], g_F2[ROWS], g_T[ROWS];     // per-row softmax factors
__device__ unsigned g_bits[(size_t)ROWS * (Nn / 32)];   // 8 MB adjacency bitmask
__device__ __half g_hp[(size_t)ROWS * Dd];              // 8 MB h_prime (fp16)
__device__ __half g_FT[(size_t)Bz * Dd * Nn];           // 8 MB feat^T (fp16)
__device__ __half g_WT[(size_t)Dd * Dd];                // W^T (fp16)

// ---------------- helpers ----------------
__device__ __forceinline__ uint32_t smem_u32(const void* p) {
    uint32_t a;
    asm("{ .reg .u64 t; cvta.to.shared.u64 t, %1; cvt.u32.u64 %0, t; }" : "=r"(a) : "l"(p));
    return a;
}
__device__ __forceinline__ uint32_t h2_as_u32(__half2 h) {
    uint32_t u;
    __builtin_memcpy(&u, &h, sizeof(u));
    return u;
}
__device__ __forceinline__ float2 u32_as_f2(uint32_t u) {
    __half2 h;
    __builtin_memcpy(&h, &u, sizeof(u));
    return __half22float2(h);
}
__device__ __forceinline__ void cp_async16(uint32_t dst, const void* src) {
    asm volatile("cp.async.cg.shared.global [%0], [%1], 16;" :: "r"(dst), "l"(src));
}
#define CP_COMMIT()  asm volatile("cp.async.commit_group;" ::: "memory")
#define CP_WAIT(n)   asm volatile("cp.async.wait_group %0;" :: "n"(n) : "memory")

// m16n8k16 fp16 warp MMA, fp32 accumulate
__device__ __forceinline__ void mma_f16(float* c, uint32_t a0, uint32_t a1,
                                        uint32_t a2, uint32_t a3,
                                        uint32_t b0, uint32_t b1) {
    asm volatile(
        "mma.sync.aligned.m16n8k16.row.col.f32.f16.f16.f32 "
        "{%0,%1,%2,%3}, {%4,%5,%6,%7}, {%8,%9}, {%0,%1,%2,%3};"
        : "+f"(c[0]), "+f"(c[1]), "+f"(c[2]), "+f"(c[3])
        : "r"(a0), "r"(a1), "r"(a2), "r"(a3), "r"(b0), "r"(b1));
}

// ---------------- K0: u1 = W @ a1, u2 = W @ a2 ----------------
__global__ void k_u(const float* __restrict__ W, const float* __restrict__ a1,
                    const float* __restrict__ a2) {
    __shared__ float s1[Dd], s2[Dd];
    int t = threadIdx.x;
    s1[t] = a1[t]; s2[t] = a2[t];
    __syncthreads();
    const float* row = W + (size_t)t * Dd;
    float acc1 = 0.f, acc2 = 0.f;
    #pragma unroll 8
    for (int d = 0; d < Dd; d++) { float w = row[d]; acc1 += w * s1[d]; acc2 += w * s2[d]; }
    g_u1[t] = acc1; g_u2[t] = acc2;
}

// ---------------- K1: Ax, Ay ----------------
__global__ void __launch_bounds__(256) k_axay(const float* __restrict__ feat) {
    int row = blockIdx.x * 8 + (threadIdx.x >> 5);
    int lane = threadIdx.x & 31;
    const float* f = feat + (size_t)row * Dd;
    float a = 0.f, b = 0.f;
    #pragma unroll
    for (int k = lane; k < Dd; k += 32) { float v = f[k]; a += v * g_u1[k]; b += v * g_u2[k]; }
    #pragma unroll
    for (int o = 16; o; o >>= 1) {
        a += __shfl_xor_sync(0xffffffffu, a, o);
        b += __shfl_xor_sync(0xffffffffu, b, o);
    }
    if (lane == 0) { g_Ax[row] = a; g_Ay[row] = b; }
}

// ---------------- K1b: per-batch max Ax ----------------
__global__ void k_bmax() {
    int b = blockIdx.x, t = threadIdx.x;
    __shared__ float sr[8];
    const float* A = g_Ax + (size_t)b * Nn;
    float mx = -3.4e38f;
    for (int i = t; i < Nn; i += 256) mx = fmaxf(mx, A[i]);
    #pragma unroll
    for (int o = 16; o; o >>= 1) mx = fmaxf(mx, __shfl_xor_sync(0xffffffffu, mx, o));
    if ((t & 31) == 0) sr[t >> 5] = mx;
    __syncthreads();
    if (t == 0) {
        float v = sr[0];
        #pragma unroll
        for (int w = 1; w < 8; w++) v = fmaxf(v, sr[w]);
        g_mb[b] = v;
    }
}

// ---------------- K1c: packed G = (exp(Ax-mb), exp(0.2(Ax-mb))) fp16 ----------------
__global__ void k_exp() {
    int i = blockIdx.x * 256 + threadIdx.x;
    float mb = g_mb[i >> 12];
    float a = g_Ax[i] - mb;
    __half2 h = __floats2half2_rn(expf(a), expf(ALPHA_F * a));
    g_G[i] = h2_as_u32(h);
}

// ---------------- K1d: feat^T (fp16) ----------------
__global__ void k_transpose(const float* __restrict__ feat) {
    __shared__ float tile[32][33];
    int j0 = blockIdx.x * 32, d0 = blockIdx.y * 32, b = blockIdx.z;
    int tx = threadIdx.x, ty = threadIdx.y;
    const float* fb = feat + (size_t)b * Nn * Dd;
    #pragma unroll
    for (int r = 0; r < 4; r++)
        tile[ty + r * 8][tx] = fb[(size_t)(j0 + ty + r * 8) * Dd + d0 + tx];
    __syncthreads();
    __half* ob = g_FT + (size_t)b * Dd * Nn;
    #pragma unroll
    for (int r = 0; r < 4; r++)
        ob[(size_t)(d0 + ty + r * 8) * Nn + j0 + tx] = __float2half_rn(tile[tx][ty + r * 8]);
}

// ---------------- K1e: W^T (fp16) ----------------
__global__ void k_wt(const float* __restrict__ W) {
    __shared__ float tile[32][33];
    int k0 = blockIdx.x * 32, n0 = blockIdx.y * 32;
    int tx = threadIdx.x, ty = threadIdx.y;
    #pragma unroll
    for (int r = 0; r < 4; r++)
        tile[ty + r * 8][tx] = W[(size_t)(k0 + ty + r * 8) * Dd + n0 + tx];
    __syncthreads();
    #pragma unroll
    for (int r = 0; r < 4; r++)
        g_WT[(size_t)(n0 + ty + r * 8) * Dd + k0 + tx] = __float2half_rn(tile[tx][ty + r * 8]);
}

// ---------------- K2: row stats + bitmask (packed-G streaming pass) ----------------
__global__ void __launch_bounds__(256) k_rowstats(const int* __restrict__ adj) {
    __shared__ unsigned sG[Nn];           // 16 KB packed (G1,G2)
    __shared__ float srM[8], srS1[8], srS2[8];

    int rb = blockIdx.x * 8;
    int b  = rb >> 12;
    int t  = threadIdx.x;
    float mb = g_mb[b];

    const uint4* gg = (const uint4*)(g_G + (size_t)b * Nn);
    #pragma unroll
    for (int i = 0; i < 4; i++) ((uint4*)sG)[t + i * 256] = gg[t + i * 256];
    __syncthreads();

    for (int rr = 0; rr < 8; rr++) {
        int row = rb + rr;
        float Ay = g_Ay[row];
        float Tp = __expf(-Ay - mb);
        const int4* arow = (const int4*)(adj + (size_t)row * Nn);

        float mxG = 0.f, S1 = 0.f, S2 = 0.f;
        #pragma unroll
        for (int q = 0; q < 4; q++) {
            int4 a4 = arow[q * 256 + t];
            uint4 gv = ((const uint4*)sG)[q * 256 + t];
            unsigned gva[4] = { gv.x, gv.y, gv.z, gv.w };
            int av[4] = { a4.x, a4.y, a4.z, a4.w };
            unsigned nib = 0u;
            #pragma unroll
            for (int r = 0; r < 4; r++) {
                if (av[r] > 0) {
                    nib |= 1u << r;
                    float2 f = u32_as_f2(gva[r]);
                    mxG = fmaxf(mxG, f.x);
                    if (f.x > Tp) S1 += f.x; else S2 += f.y;
                }
            }
            unsigned v = nib << ((t & 7) * 4);
            v |= __shfl_xor_sync(0xffffffffu, v, 1);
            v |= __shfl_xor_sync(0xffffffffu, v, 2);
            v |= __shfl_xor_sync(0xffffffffu, v, 4);
            if ((t & 7) == 0)
                g_bits[(size_t)row * (Nn / 32) + q * 32 + (t >> 3)] = v;
        }

        #pragma unroll
        for (int o = 16; o; o >>= 1) {
            mxG = fmaxf(mxG, __shfl_xor_sync(0xffffffffu, mxG, o));
            S1 += __shfl_xor_sync(0xffffffffu, S1, o);
            S2 += __shfl_xor_sync(0xffffffffu, S2, o);
        }
        if ((t & 31) == 0) { int w = t >> 5; srM[w] = mxG; srS1[w] = S1; srS2[w] = S2; }
        __syncthreads();
        if (t == 0) {
            float M = srM[0], s1 = srS1[0], s2 = srS2[0];
            #pragma unroll
            for (int w = 1; w < 8; w++) {
                M = fmaxf(M, srM[w]); s1 += srS1[w]; s2 += srS2[w];
            }
            float m0 = Ay + mb + logf(M);               // max masked z
            float m  = m0 > 0.f ? m0 : ALPHA_F * m0;    // leakyrelu(max) = max(leakyrelu)
            float eP = __expf(Ay + mb - m);
            float eN = __expf(ALPHA_F * (Ay + mb) - m);
            float invs = 1.f / (eP * s1 + eN * s2);
            g_F1[row] = eP * invs;
            g_F2[row] = eN * invs;
            g_T[row]  = Tp;
        }
        __syncthreads();
    }
}

// ---------------- K3: h_prime = P @ feat via fp16 MMA ----------------
// One CTA per 128-row stripe, full 256 d-cols. 8 warps, warp tile 64x64.
// K = 4096 in 64 chunks of 64, double-buffered cp.async for F; P built once.
#define AB_G  0
#define AB_P  16384
#define PBUF_B (128 * 144)                  // 18432
#define AB_F  (AB_P + 2 * PBUF_B)           // 53248
#define FBUF_B (256 * 144)                  // 36864
#define AT_SMEM_BYTES (AB_F + 2 * FBUF_B)   // 126976

__global__ void __launch_bounds__(256) k_attn_mma() {
    extern __shared__ char smc[];
    const uint32_t sb = smem_u32(smc);
    unsigned* sG = (unsigned*)(smc + AB_G);
    const int t = threadIdx.x;
    const int wid = t >> 5, lane = t & 31;
    const int g = lane >> 2, tig = lane & 3;
    const int rowbase = blockIdx.x * 128;
    const int b = rowbase >> 12;            // 4096 % 128 == 0
    const __half* FTb = g_FT + (size_t)b * Dd * Nn;

    // stage packed G for this batch (16 KB)
    {
        const uint4* gg = (const uint4*)(g_G + (size_t)b * Nn);
        #pragma unroll
        for (int i = 0; i < 4; i++) ((uint4*)sG)[t + i * 256] = gg[t + i * 256];
    }
    const int ip = t >> 1, jh = t & 1;      // P-build: row ip, 32-j half jh
    const int grow = rowbase + ip;
    const float F1 = g_F1[grow], F2 = g_F2[grow], T = g_T[grow];
    const unsigned* bitsrow = g_bits + (size_t)grow * (Nn / 32);
    __syncthreads();

    // prefetch F chunk 0 (256 d-rows x 64 j fp16 = 32 KB)
    {
        #pragma unroll
        for (int i = 0; i < 8; i++) {
            int f = t + i * 256;
            int dr = f >> 3, cq = f & 7;
            cp_async16(sb + AB_F + dr * 144 + cq * 16,
                       FTb + (size_t)dr * Nn + cq * 8);
        }
        CP_COMMIT();
    }

    const int mbase = (wid & 1) * 64;
    const int nbase = (wid >> 1) * 64;
    float acc[4][8][4];
    #pragma unroll
    for (int mt = 0; mt < 4; mt++)
        #pragma unroll
        for (int nt = 0; nt < 8; nt++)
            #pragma unroll
            for (int r = 0; r < 4; r++) acc[mt][nt][r] = 0.f;

    const int NCH = Nn / 64;
    for (int c = 0; c < NCH; c++) {
        const int buf = c & 1;
        char* Pb = smc + AB_P + buf * PBUF_B;
        const uint32_t* sPw = (const uint32_t*)(smc + AB_P + buf * PBUF_B);
        const uint32_t* sFw = (const uint32_t*)(smc + AB_F + buf * FBUF_B);
        const int j0 = c * 64;

        // prefetch F(c+1)
        if (c + 1 < NCH) {
            uint32_t dstb = sb + AB_F + (1 - buf) * FBUF_B;
            const __half* src = FTb + j0 + 64;
            #pragma unroll
            for (int i = 0; i < 8; i++) {
                int f = t + i * 256;
                int dr = f >> 3, cq = f & 7;
                cp_async16(dstb + dr * 144 + cq * 16,
                           src + (size_t)dr * Nn + cq * 8);
            }
            CP_COMMIT();
        }

        // build P(c): row ip, 32 j of half jh, packed fp16
        {
            unsigned wb = bitsrow[2 * c + jh];
            const unsigned* gp = sG + j0 + jh * 32;
            #pragma unroll
            for (int q = 0; q < 4; q++) {
                __half2 h[4];
                #pragma unroll
                for (int d = 0; d < 4; d++) {
                    int jj0 = q * 8 + d * 2;
                    float2 fa = u32_as_f2(gp[jj0]);
                    float2 fb = u32_as_f2(gp[jj0 + 1]);
                    float pa = (fa.x > T) ? fa.x * F1 : fa.y * F2;
                    float pb = (fb.x > T) ? fb.x * F1 : fb.y * F2;
                    pa = ((wb >> jj0) & 1u) ? pa : 0.f;
                    pb = ((wb >> (jj0 + 1)) & 1u) ? pb : 0.f;
                    h[d] = __floats2half2_rn(pa, pb);
                }
                *(uint4*)(Pb + ip * 144 + jh * 64 + q * 16) =
                    make_uint4(h2_as_u32(h[0]), h2_as_u32(h[1]),
                               h2_as_u32(h[2]), h2_as_u32(h[3]));
            }
        }

        if (c + 1 < NCH) { CP_WAIT(1); } else { CP_WAIT(0); }
        __syncthreads();

        // MMA: 4 k16 steps over this K64 chunk
        #pragma unroll
        for (int k16 = 0; k16 < 4; k16++) {
            const int kw = k16 * 8 + tig;        // uint (half2) offset within 36-uint row
            uint32_t af[4][4];
            #pragma unroll
            for (int mt = 0; mt < 4; mt++) {
                int r0 = (mbase + mt * 16 + g) * 36 + kw;
                af[mt][0] = sPw[r0];
                af[mt][2] = sPw[r0 + 4];
                af[mt][1] = sPw[r0 + 8 * 36];
                af[mt][3] = sPw[r0 + 8 * 36 + 4];
            }
            uint32_t bf[8][2];
            #pragma unroll
            for (int nt = 0; nt < 8; nt++) {
                int n0 = (nbase + nt * 8 + g) * 36 + kw;
                bf[nt][0] = sFw[n0];
                bf[nt][1] = sFw[n0 + 4];
            }
            #pragma unroll
            for (int mt = 0; mt < 4; mt++)
                #pragma unroll
                for (int nt = 0; nt < 8; nt++)
                    mma_f16(acc[mt][nt], af[mt][0], af[mt][1], af[mt][2], af[mt][3],
                            bf[nt][0], bf[nt][1]);
        }
        __syncthreads();
    }

    // epilogue: write h_prime (fp16)
    #pragma unroll
    for (int mt = 0; mt < 4; mt++) {
        int r0 = rowbase + mbase + mt * 16 + g;
        #pragma unroll
        for (int nt = 0; nt < 8; nt++) {
            int col = nbase + nt * 8 + 2 * tig;
            *(__half2*)&g_hp[(size_t)r0 * Dd + col] =
                __floats2half2_rn(acc[mt][nt][0], acc[mt][nt][1]);
            *(__half2*)&g_hp[(size_t)(r0 + 8) * Dd + col] =
                __floats2half2_rn(acc[mt][nt][2], acc[mt][nt][3]);
        }
    }
}

// ---------------- K4: out = elu(h_prime @ W) via fp16 MMA ----------------
// CTA 128 x 256 (full N), 8 warps 64x64, K = 256 in 4 chunks of 64.
#define KO_SA 0
#define KO_SW 18432                         // 128*144
#define KO_SMEM_BYTES (18432 + 36864)       // 55296

__global__ void __launch_bounds__(256) k_out_mma(float* __restrict__ out) {
    extern __shared__ char smc[];
    const uint32_t sb = smem_u32(smc);
    const int t = threadIdx.x;
    const int wid = t >> 5, lane = t & 31;
    const int g = lane >> 2, tig = lane & 3;
    const int rowbase = blockIdx.x * 128;
    const int mbase = (wid & 1) * 64;
    const int nbase = (wid >> 1) * 64;
    const uint32_t* sAw = (const uint32_t*)(smc + KO_SA);
    const uint32_t* sWw = (const uint32_t*)(smc + KO_SW);

    float acc[4][8][4];
    #pragma unroll
    for (int mt = 0; mt < 4; mt++)
        #pragma unroll
        for (int nt = 0; nt < 8; nt++)
            #pragma unroll
            for (int r = 0; r < 4; r++) acc[mt][nt][r] = 0.f;

    for (int k0 = 0; k0 < Dd; k0 += 64) {
        if (k0) __syncthreads();
        // A: h_prime[rowbase..+127, k0..k0+63] fp16 (16 KB, 4 cp16/thread)
        #pragma unroll
        for (int i = 0; i < 4; i++) {
            int f = t + i * 256;
            int rr = f >> 3, cq = f & 7;
            cp_async16(sb + KO_SA + rr * 144 + cq * 16,
                       g_hp + (size_t)(rowbase + rr) * Dd + k0 + cq * 8);
        }
        // W^T[n=0..255, k0..k0+63] fp16 (32 KB, 8 cp16/thread)
        #pragma unroll
        for (int i = 0; i < 8; i++) {
            int f = t + i * 256;
            int nr = f >> 3, cq = f & 7;
            cp_async16(sb + KO_SW + nr * 144 + cq * 16,
                       g_WT + (size_t)nr * Dd + k0 + cq * 8);
        }
        CP_COMMIT();
        CP_WAIT(0);
        __syncthreads();

        #pragma unroll
        for (int k16 = 0; k16 < 4; k16++) {
            const int kw = k16 * 8 + tig;
            uint32_t af[4][4];
            #pragma unroll
            for (int mt = 0; mt < 4; mt++) {
                int r0 = (mbase + mt * 16 + g) * 36 + kw;
                af[mt][0] = sAw[r0];
                af[mt][2] = sAw[r0 + 4];
                af[mt][1] = sAw[r0 + 8 * 36];
                af[mt][3] = sAw[r0 + 8 * 36 + 4];
            }
            uint32_t bf[8][2];
            #pragma unroll
            for (int nt = 0; nt < 8; nt++) {
                int n0 = (nbase + nt * 8 + g) * 36 + kw;
                bf[nt][0] = sWw[n0];
                bf[nt][1] = sWw[n0 + 4];
            }
            #pragma unroll
            for (int mt = 0; mt < 4; mt++)
                #pragma unroll
                for (int nt = 0; nt < 8; nt++)
                    mma_f16(acc[mt][nt], af[mt][0], af[mt][1], af[mt][2], af[mt][3],
                            bf[nt][0], bf[nt][1]);
        }
    }

    // epilogue: ELU + fp32 store
    #pragma unroll
    for (int mt = 0; mt < 4; mt++) {
        int r0 = rowbase + mbase + mt * 16 + g;
        #pragma unroll
        for (int nt = 0; nt < 8; nt++) {
            int col = nbase + nt * 8 + 2 * tig;
            float v0 = acc[mt][nt][0], v1 = acc[mt][nt][1];
            float v2 = acc[mt][nt][2], v3 = acc[mt][nt][3];
            v0 = v0 > 0.f ? v0 : expm1f(v0);
            v1 = v1 > 0.f ? v1 : expm1f(v1);
            v2 = v2 > 0.f ? v2 : expm1f(v2);
            v3 = v3 > 0.f ? v3 : expm1f(v3);
            *(float2*)&out[(size_t)r0 * Dd + col] = make_float2(v0, v1);
            *(float2*)&out[(size_t)(r0 + 8) * Dd + col] = make_float2(v2, v3);
        }
    }
}

// ---------------- launch ----------------
extern "C" void kernel_launch(void* const* d_in, const int* in_sizes, int n_in,
                              void* d_out, int out_size) {
    const float* feat = (const float*)d_in[0];
    const int*   adj  = (const int*)d_in[1];
    const float* W    = (const float*)d_in[2];
    const float* a1   = (const float*)d_in[3];
    const float* a2   = (const float*)d_in[4];
    float* out = (float*)d_out;

    cudaFuncSetAttribute(k_attn_mma, cudaFuncAttributeMaxDynamicSharedMemorySize, AT_SMEM_BYTES);
    cudaFuncSetAttribute(k_out_mma, cudaFuncAttributeMaxDynamicSharedMemorySize, KO_SMEM_BYTES);

    k_u<<<1, 256>>>(W, a1, a2);
    k_axay<<<ROWS / 8, 256>>>(feat);
    k_bmax<<<Bz, 256>>>();
    k_exp<<<ROWS / 256, 256>>>();
    k_transpose<<<dim3(Nn / 32, Dd / 32, Bz), dim3(32, 8)>>>(feat);
    k_wt<<<dim3(Dd / 32, Dd / 32), dim3(32, 8)>>>(W);
    k_rowstats<<<ROWS / 8, 256>>>(adj);
    k_attn_mma<<<ROWS / 128, 256, AT_SMEM_BYTES>>>();
    k_out_mma<<<ROWS / 128, 256, KO_SMEM_BYTES>>>(out);
}